// round 10
// baseline (speedup 1.0000x reference)
#include <cuda_runtime.h>
#include <cuda_bf16.h>

// ---------------------------------------------------------------------------
// YOLACT bbox + mask post-processing, full pipeline.
// Inputs (metadata order): cls_score0..4, bbox_pred0..4, coeff_pred0..4, proto
// Output (float32, concatenated): cls_dets[64,100,5], labels[64,100],
//                                 masks[64,80,80,100]
// ---------------------------------------------------------------------------

#define NA      6402          // total anchors
#define PITCH   6416          // padded anchor pitch for score scratch
#define NCLS    80            // foreground classes
#define TOPK    200
#define NBATCH  64
#define NFLAT   (NCLS*TOPK)   // 16000
#define MAXNUM  100
#define NCOEF   32
#define NPIX    6400          // 80*80
#define MAXR    4.135166556742356f
#define SCORE_THR 0.05f
#define IOU_THR   0.5f

#define OFF_LAB  ((size_t)NBATCH*MAXNUM*5)           // 32000
#define OFF_MASK (OFF_LAB + (size_t)NBATCH*MAXNUM)   // 38400

// ------------------------- device scratch ----------------------------------
__device__ float  g_scores[(size_t)NBATCH*NCLS*PITCH];   // [b][c][anchor]
__device__ float4 g_boxes [NBATCH*NA];                   // decoded boxes
__device__ int    g_order [NBATCH*NCLS*TOPK];            // per-class ranked anchor ids
__device__ float  g_tscore[NBATCH*NCLS*TOPK];            // ranked scores -> masked scores
__device__ int    g_selidx[NBATCH*MAXNUM];
__device__ float  g_selval[NBATCH*MAXNUM];
__device__ float  g_coeff [NBATCH*MAXNUM*NCOEF];

// ------------------------- level helpers -----------------------------------
__device__ __forceinline__ void get_lvl(int A, int& lvl, int& i) {
    if (A < 4800)      { lvl = 0; i = A; }
    else if (A < 6000) { lvl = 1; i = A - 4800; }
    else if (A < 6300) { lvl = 2; i = A - 6000; }
    else if (A < 6375) { lvl = 3; i = A - 6300; }
    else               { lvl = 4; i = A - 6375; }
}
__device__ __forceinline__ int lvl_hw(int lvl) {
    const int hw[5] = {1600, 400, 100, 25, 9};
    return hw[lvl];
}
__device__ __forceinline__ int lvl_f(int lvl) {
    const int f[5] = {40, 20, 10, 5, 3};
    return f[lvl];
}
__device__ __forceinline__ int lvl_bs(int lvl) {
    const int bs[5] = {8, 16, 32, 64, 128};
    return bs[lvl];
}
__device__ __forceinline__ const float* sel_ptr(int lvl, const float* p0, const float* p1,
                                                const float* p2, const float* p3, const float* p4) {
    return lvl == 0 ? p0 : lvl == 1 ? p1 : lvl == 2 ? p2 : lvl == 3 ? p3 : p4;
}

// sortable key for possibly-negative floats (handles the -1 masked values)
__device__ __forceinline__ unsigned f2key(float f) {
    unsigned u = __float_as_uint(f);
    return (u & 0x80000000u) ? ~u : (u | 0x80000000u);
}
__device__ __forceinline__ float key2f(unsigned k) {
    unsigned u = (k & 0x80000000u) ? (k & 0x7FFFFFFFu) : ~k;
    return __uint_as_float(u);
}

// ---------------------------------------------------------------------------
// K1: softmax over 81 classes per anchor; store 80 fg scores transposed.
// ---------------------------------------------------------------------------
__global__ void __launch_bounds__(256)
k_softmax(const float* __restrict__ c0, const float* __restrict__ c1,
          const float* __restrict__ c2, const float* __restrict__ c3,
          const float* __restrict__ c4) {
    int A = blockIdx.x * 256 + threadIdx.x;
    int b = blockIdx.y;
    if (A >= NA) return;
    int lvl, i; get_lvl(A, lvl, i);
    int HW = lvl_hw(lvl);
    int pos = i / 3, a = i - pos * 3;
    const float* base = sel_ptr(lvl, c0, c1, c2, c3, c4)
                        + ((size_t)b * 243 + a * 81) * HW + pos;
    float m = -1e30f;
    #pragma unroll 4
    for (int c = 0; c < 81; c++) m = fmaxf(m, base[(size_t)c * HW]);
    float s = 0.f;
    #pragma unroll 4
    for (int c = 0; c < 81; c++) s += expf(base[(size_t)c * HW] - m);
    float inv = 1.0f / s;
    float* o = g_scores + (size_t)b * NCLS * PITCH + A;
    #pragma unroll 4
    for (int c = 0; c < 80; c++)
        o[(size_t)c * PITCH] = expf(base[(size_t)c * HW] - m) * inv;
}

// ---------------------------------------------------------------------------
// K2: anchor generation (fp64, matching numpy) + delta2bbox decode.
// ---------------------------------------------------------------------------
__global__ void __launch_bounds__(256)
k_decode(const float* __restrict__ b0, const float* __restrict__ b1,
         const float* __restrict__ b2, const float* __restrict__ b3,
         const float* __restrict__ b4) {
    int A = blockIdx.x * 256 + threadIdx.x;
    int b = blockIdx.y;
    if (A >= NA) return;
    int lvl, i; get_lvl(A, lvl, i);
    int HW = lvl_hw(lvl), f = lvl_f(lvl), bs = lvl_bs(lvl);
    int pos = i / 3, a = i - pos * 3;
    int x = pos % f, y = pos / f;

    const double hrD[3] = {0.7071067811865476, 1.0, 1.4142135623730951};
    double hr = hrD[a], wr = 1.0 / hr;
    double bsd = (double)bs;
    double ws = bsd * wr * 3.0, hs = bsd * hr * 3.0;
    double c = bsd * 0.5;
    double sx = (double)(x * bs), sy = (double)(y * bs);
    float ax1 = (float)((c - 0.5 * ws) + sx);
    float ay1 = (float)((c - 0.5 * hs) + sy);
    float ax2 = (float)((c + 0.5 * ws) + sx);
    float ay2 = (float)((c + 0.5 * hs) + sy);

    const float* bp = sel_ptr(lvl, b0, b1, b2, b3, b4)
                      + ((size_t)b * 12 + a * 4) * HW + pos;
    float d0 = bp[0] * 0.1f;
    float d1 = bp[(size_t)HW] * 0.1f;
    float d2 = bp[(size_t)2 * HW] * 0.2f;
    float d3 = bp[(size_t)3 * HW] * 0.2f;

    float px = (ax1 + ax2) * 0.5f, py = (ay1 + ay2) * 0.5f;
    float pw = ax2 - ax1,          ph = ay2 - ay1;
    float dw = fminf(fmaxf(d2, -MAXR), MAXR);
    float dh = fminf(fmaxf(d3, -MAXR), MAXR);
    float gx = px + pw * d0;
    float gy = py + ph * d1;
    float gw = pw * expf(dw);
    float gh = ph * expf(dh);
    float x1 = fminf(fmaxf(gx - 0.5f * gw, 0.f), 320.f);
    float y1 = fminf(fmaxf(gy - 0.5f * gh, 0.f), 320.f);
    float x2 = fminf(fmaxf(gx + 0.5f * gw, 0.f), 320.f);
    float y2 = fminf(fmaxf(gy + 0.5f * gh, 0.f), 320.f);
    g_boxes[b * NA + A] = make_float4(x1, y1, x2, y2);
}

// ---------------------------------------------------------------------------
// K3: per-(batch,class) exact top-200 via 4-pass radix select + bitonic sort.
// Reproduces jnp.argsort(-s) stable semantics: desc score, asc anchor index.
// ---------------------------------------------------------------------------
__global__ void __launch_bounds__(256)
k_topk_class() {
    int c = blockIdx.x, b = blockIdx.y, tid = threadIdx.x;
    __shared__ unsigned sv[NA];
    __shared__ unsigned hist[256];
    __shared__ unsigned s_scan[256];
    __shared__ unsigned long long cand[256];
    __shared__ unsigned s_sel, s_k, s_cnt;

    const float* row = g_scores + (size_t)(b * NCLS + c) * PITCH;
    for (int i = tid; i < NA; i += 256) sv[i] = __float_as_uint(row[i]);  // scores>0

    unsigned prefix = 0, mask = 0;
    if (tid == 0) s_k = TOPK;
    __syncthreads();

    for (int shift = 24; shift >= 0; shift -= 8) {
        hist[tid] = 0; __syncthreads();
        for (int i = tid; i < NA; i += 256) {
            unsigned v = sv[i];
            if ((v & mask) == prefix) atomicAdd(&hist[(v >> shift) & 255], 1);
        }
        __syncthreads();
        if (tid == 0) {
            unsigned k = s_k, cum = 0;
            for (int bin = 255; bin >= 0; --bin) {
                cum += hist[bin];
                if (cum >= k) { s_sel = (unsigned)bin; s_k = k - (cum - hist[bin]); break; }
            }
        }
        __syncthreads();
        prefix |= s_sel << shift;
        mask   |= 0xFFu << shift;
        __syncthreads();
    }
    unsigned T = prefix, krem = s_k;     // take krem elements equal to T (lowest idx)
    if (tid == 0) s_cnt = 0;
    __syncthreads();

    for (int i = tid; i < NA; i += 256) {
        unsigned v = sv[i];
        if (v > T) {
            unsigned p = atomicAdd(&s_cnt, 1);
            cand[p] = ((unsigned long long)v << 32) | (unsigned)(~i);
        }
    }
    __syncthreads();
    unsigned cntgt = s_cnt;              // == TOPK - krem

    const int CH = (NA + 255) / 256;     // 26
    int lo = tid * CH, hi = min(lo + CH, NA);
    unsigned cnt = 0;
    for (int i = lo; i < hi; i++) if (sv[i] == T) cnt++;
    s_scan[tid] = cnt; __syncthreads();
    for (int d = 1; d < 256; d <<= 1) {
        unsigned t2 = (tid >= d) ? s_scan[tid - d] : 0;
        __syncthreads();
        s_scan[tid] += t2;
        __syncthreads();
    }
    unsigned r = (tid == 0) ? 0 : s_scan[tid - 1];
    for (int i = lo; i < hi; i++) {
        if (sv[i] == T) {
            if (r < krem) cand[cntgt + r] = ((unsigned long long)T << 32) | (unsigned)(~i);
            r++;
        }
    }
    if (tid >= TOPK) cand[tid] = 0ULL;   // pad 200..255
    __syncthreads();

    // bitonic sort 256, descending (keys unique -> stability irrelevant)
    for (int size = 2; size <= 256; size <<= 1)
        for (int stride = size >> 1; stride > 0; stride >>= 1) {
            __syncthreads();
            int j = tid ^ stride;
            if (j > tid) {
                bool desc = ((tid & size) == 0);
                unsigned long long a = cand[tid], bb = cand[j];
                if ((a < bb) == desc) { cand[tid] = bb; cand[j] = a; }
            }
        }
    __syncthreads();

    if (tid < TOPK) {
        unsigned long long kk = cand[tid];
        int base = (b * NCLS + c) * TOPK + tid;
        g_order[base]  = (int)(~(unsigned)kk);
        g_tscore[base] = __uint_as_float((unsigned)(kk >> 32));
    }
}

// ---------------------------------------------------------------------------
// K4: fast-NMS. Column j = max IoU against ranks i<j; write masked score.
// ---------------------------------------------------------------------------
__global__ void __launch_bounds__(256)
k_nms() {
    int c = blockIdx.x, b = blockIdx.y, tid = threadIdx.x;
    __shared__ float4 sb[TOPK];
    __shared__ float  ss[TOPK];
    int base = (b * NCLS + c) * TOPK;
    if (tid < TOPK) {
        int a = g_order[base + tid];
        sb[tid] = g_boxes[b * NA + a];
        ss[tid] = g_tscore[base + tid];
    }
    __syncthreads();
    if (tid < TOPK) {
        float4 bj = sb[tid];
        float areaj = (bj.z - bj.x) * (bj.w - bj.y);
        float mx = 0.f;
        for (int i = 0; i < tid; i++) {
            float4 bi = sb[i];
            float lx = fmaxf(bi.x, bj.x), ly = fmaxf(bi.y, bj.y);
            float rx = fminf(bi.z, bj.z), ry = fminf(bi.w, bj.w);
            float w = fmaxf(rx - lx, 0.f), h = fmaxf(ry - ly, 0.f);
            float ov = w * h;
            float ai = (bi.z - bi.x) * (bi.w - bi.y);
            float un = fmaxf(ai + areaj - ov, 1e-6f);
            mx = fmaxf(mx, ov / un);
        }
        float s = ss[tid];
        bool keep = (mx <= IOU_THR) && (s > SCORE_THR);
        g_tscore[base + tid] = keep ? s : -1.0f;
    }
}

// ---------------------------------------------------------------------------
// K5: per-batch global top-100 over 16000 masked scores (lax.top_k semantics).
// ---------------------------------------------------------------------------
__global__ void __launch_bounds__(256)
k_topk_final() {
    int b = blockIdx.x, tid = threadIdx.x;
    const float* vals = g_tscore + (size_t)b * NFLAT;
    __shared__ unsigned hist[256];
    __shared__ unsigned s_scan[256];
    __shared__ unsigned long long cand[128];
    __shared__ unsigned s_sel, s_k, s_cnt;

    unsigned prefix = 0, mask = 0;
    if (tid == 0) s_k = MAXNUM;
    __syncthreads();

    for (int shift = 24; shift >= 0; shift -= 8) {
        hist[tid] = 0; __syncthreads();
        for (int i = tid; i < NFLAT; i += 256) {
            unsigned v = f2key(vals[i]);
            if ((v & mask) == prefix) atomicAdd(&hist[(v >> shift) & 255], 1);
        }
        __syncthreads();
        if (tid == 0) {
            unsigned k = s_k, cum = 0;
            for (int bin = 255; bin >= 0; --bin) {
                cum += hist[bin];
                if (cum >= k) { s_sel = (unsigned)bin; s_k = k - (cum - hist[bin]); break; }
            }
        }
        __syncthreads();
        prefix |= s_sel << shift;
        mask   |= 0xFFu << shift;
        __syncthreads();
    }
    unsigned T = prefix, krem = s_k;
    if (tid == 0) s_cnt = 0;
    __syncthreads();

    for (int i = tid; i < NFLAT; i += 256) {
        unsigned v = f2key(vals[i]);
        if (v > T) {
            unsigned p = atomicAdd(&s_cnt, 1);
            cand[p] = ((unsigned long long)v << 32) | (unsigned)(~i);
        }
    }
    __syncthreads();
    unsigned cntgt = s_cnt;

    const int CH = (NFLAT + 255) / 256;  // 63
    int lo = tid * CH, hi = min(lo + CH, NFLAT);
    unsigned cnt = 0;
    for (int i = lo; i < hi; i++) if (f2key(vals[i]) == T) cnt++;
    s_scan[tid] = cnt; __syncthreads();
    for (int d = 1; d < 256; d <<= 1) {
        unsigned t2 = (tid >= d) ? s_scan[tid - d] : 0;
        __syncthreads();
        s_scan[tid] += t2;
        __syncthreads();
    }
    unsigned r = (tid == 0) ? 0 : s_scan[tid - 1];
    for (int i = lo; i < hi; i++) {
        if (f2key(vals[i]) == T) {
            if (r < krem) cand[cntgt + r] = ((unsigned long long)T << 32) | (unsigned)(~i);
            r++;
        }
    }
    if (tid >= MAXNUM && tid < 128) cand[tid] = 0ULL;
    __syncthreads();

    for (int size = 2; size <= 128; size <<= 1)
        for (int stride = size >> 1; stride > 0; stride >>= 1) {
            __syncthreads();
            if (tid < 128) {
                int j = tid ^ stride;
                if (j > tid) {
                    bool desc = ((tid & size) == 0);
                    unsigned long long a = cand[tid], bb = cand[j];
                    if ((a < bb) == desc) { cand[tid] = bb; cand[j] = a; }
                }
            }
        }
    __syncthreads();

    if (tid < MAXNUM) {
        unsigned long long kk = cand[tid];
        g_selidx[b * MAXNUM + tid] = (int)(~(unsigned)kk);
        g_selval[b * MAXNUM + tid] = key2f((unsigned)(kk >> 32));
    }
}

// ---------------------------------------------------------------------------
// K6: gather cls_dets, labels, and the 32 mask coefficients per detection.
// ---------------------------------------------------------------------------
__global__ void __launch_bounds__(128)
k_gather(const float* __restrict__ f0, const float* __restrict__ f1,
         const float* __restrict__ f2, const float* __restrict__ f3,
         const float* __restrict__ f4, float* __restrict__ out) {
    int b = blockIdx.x, tid = threadIdx.x;
    if (tid >= MAXNUM) return;
    int flat = g_selidx[b * MAXNUM + tid];
    int cls = flat / TOPK, k = flat - cls * TOPK;
    int a = g_order[(b * NCLS + cls) * TOPK + k];
    float4 box = g_boxes[b * NA + a];
    float v = g_selval[b * MAXNUM + tid];

    float* det = out + (size_t)b * MAXNUM * 5 + (size_t)tid * 5;
    det[0] = box.x; det[1] = box.y; det[2] = box.z; det[3] = box.w; det[4] = v;
    out[OFF_LAB + (size_t)b * MAXNUM + tid] = (float)cls;

    int lvl, i; get_lvl(a, lvl, i);
    int HW = lvl_hw(lvl);
    int pos = i / 3, ar = i - pos * 3;
    const float* cp = sel_ptr(lvl, f0, f1, f2, f3, f4)
                      + ((size_t)b * 96 + ar * 32) * HW + pos;
    float* gc = g_coeff + ((size_t)b * MAXNUM + tid) * NCOEF;
    #pragma unroll
    for (int c = 0; c < NCOEF; c++) gc[c] = cp[(size_t)c * HW];
}

// ---------------------------------------------------------------------------
// K7: masks = sigmoid(proto[80,80,32] @ coeff[100,32]^T) -> [80,80,100].
// Thread = one pixel (proto row in registers), coeffs broadcast from smem,
// output staged through smem in 25-det chunks for near-coalesced stores.
// ---------------------------------------------------------------------------
__global__ void __launch_bounds__(256)
k_masks(const float* __restrict__ proto, float* __restrict__ out) {
    __shared__ float scoef[MAXNUM * NCOEF];   // 12.8 KB
    __shared__ float sout[256 * 25];          // 25.6 KB
    int b = blockIdx.y;
    int pixbase = blockIdx.x * 256;
    int tid = threadIdx.x;

    for (int i = tid; i < MAXNUM * NCOEF; i += 256)
        scoef[i] = g_coeff[(size_t)b * MAXNUM * NCOEF + i];
    __syncthreads();

    float pr[NCOEF];
    const float* pp = proto + ((size_t)b * NPIX + pixbase + tid) * NCOEF;
    #pragma unroll
    for (int c = 0; c < NCOEF; c += 4) {
        float4 t = *reinterpret_cast<const float4*>(pp + c);
        pr[c] = t.x; pr[c + 1] = t.y; pr[c + 2] = t.z; pr[c + 3] = t.w;
    }

    float* outm = out + OFF_MASK + (size_t)b * NPIX * MAXNUM;
    for (int chunk = 0; chunk < 4; chunk++) {
        int dbase = chunk * 25;
        for (int d = 0; d < 25; d++) {
            const float* cf = scoef + (dbase + d) * NCOEF;
            float acc = 0.f;
            #pragma unroll
            for (int c = 0; c < NCOEF; c++) acc = fmaf(pr[c], cf[c], acc);
            sout[tid * 25 + d] = 1.0f / (1.0f + expf(-acc));
        }
        __syncthreads();
        for (int i = tid; i < 256 * 25; i += 256) {
            int p = i / 25, d = i - p * 25;
            outm[(size_t)(pixbase + p) * MAXNUM + dbase + d] = sout[i];
        }
        __syncthreads();
    }
}

// ---------------------------------------------------------------------------
extern "C" void kernel_launch(void* const* d_in, const int* in_sizes, int n_in,
                              void* d_out, int out_size) {
    const float* cs[5]; const float* bp[5]; const float* cf[5];
    for (int i = 0; i < 5; i++) {
        cs[i] = (const float*)d_in[i];
        bp[i] = (const float*)d_in[5 + i];
        cf[i] = (const float*)d_in[10 + i];
    }
    const float* proto = (const float*)d_in[15];
    float* out = (float*)d_out;

    dim3 gA((NA + 255) / 256, NBATCH);
    k_softmax   <<<gA, 256>>>(cs[0], cs[1], cs[2], cs[3], cs[4]);
    k_decode    <<<gA, 256>>>(bp[0], bp[1], bp[2], bp[3], bp[4]);
    k_topk_class<<<dim3(NCLS, NBATCH), 256>>>();
    k_nms       <<<dim3(NCLS, NBATCH), 256>>>();
    k_topk_final<<<NBATCH, 256>>>();
    k_gather    <<<NBATCH, 128>>>(cf[0], cf[1], cf[2], cf[3], cf[4], out);
    k_masks     <<<dim3(NPIX / 256, NBATCH), 256>>>(proto, out);
}

// round 13
// speedup vs baseline: 1.5641x; 1.5641x over previous
#include <cuda_runtime.h>
#include <cuda_bf16.h>

// ---------------------------------------------------------------------------
// YOLACT bbox + mask post-processing, full pipeline.
// Inputs (metadata order): cls_score0..4, bbox_pred0..4, coeff_pred0..4, proto
// Output (float32, concatenated): cls_dets[64,100,5], labels[64,100],
//                                 masks[64,80,80,100]
// ---------------------------------------------------------------------------

#define NA      6402          // total anchors
#define PITCH   6416          // padded anchor pitch for score scratch
#define NCLS    80            // foreground classes
#define TOPK    200
#define NBATCH  64
#define NFLAT   (NCLS*TOPK)   // 16000
#define MAXNUM  100
#define NCOEF   32
#define NPIX    6400          // 80*80
#define MAXR    4.135166556742356f
#define SCORE_THR 0.05f
#define IOU_THR   0.5f
// 2^-25: RN midpoint margin so (lhs <= HALF_ULP*un) == (RN(ov/un) <= 0.5)
#define HALF_ULP  2.9802322387695312e-08f

#define OFF_LAB  ((size_t)NBATCH*MAXNUM*5)           // 32000
#define OFF_MASK (OFF_LAB + (size_t)NBATCH*MAXNUM)   // 38400

// ------------------------- device scratch ----------------------------------
__device__ float  g_scores[(size_t)NBATCH*NCLS*PITCH];   // [b][c][anchor]
__device__ float4 g_boxes [NBATCH*NA];                   // decoded boxes
__device__ int    g_order [NBATCH*NCLS*TOPK];            // per-class ranked anchor ids
__device__ float  g_tscore[NBATCH*NCLS*TOPK];            // ranked scores -> masked scores
__device__ int    g_selidx[NBATCH*MAXNUM];
__device__ float  g_selval[NBATCH*MAXNUM];
__device__ float  g_coeff [NBATCH*MAXNUM*NCOEF];

// ------------------------- level helpers -----------------------------------
__device__ __forceinline__ void get_lvl(int A, int& lvl, int& i) {
    if (A < 4800)      { lvl = 0; i = A; }
    else if (A < 6000) { lvl = 1; i = A - 4800; }
    else if (A < 6300) { lvl = 2; i = A - 6000; }
    else if (A < 6375) { lvl = 3; i = A - 6300; }
    else               { lvl = 4; i = A - 6375; }
}
__device__ __forceinline__ int lvl_hw(int lvl) {
    const int hw[5] = {1600, 400, 100, 25, 9};
    return hw[lvl];
}
__device__ __forceinline__ int lvl_f(int lvl) {
    const int f[5] = {40, 20, 10, 5, 3};
    return f[lvl];
}
__device__ __forceinline__ int lvl_bs(int lvl) {
    const int bs[5] = {8, 16, 32, 64, 128};
    return bs[lvl];
}
__device__ __forceinline__ const float* sel_ptr(int lvl, const float* p0, const float* p1,
                                                const float* p2, const float* p3, const float* p4) {
    return lvl == 0 ? p0 : lvl == 1 ? p1 : lvl == 2 ? p2 : lvl == 3 ? p3 : p4;
}

// sortable key for possibly-negative floats (handles the -1 masked values)
__device__ __forceinline__ unsigned f2key(float f) {
    unsigned u = __float_as_uint(f);
    return (u & 0x80000000u) ? ~u : (u | 0x80000000u);
}
__device__ __forceinline__ float key2f(unsigned k) {
    unsigned u = (k & 0x80000000u) ? (k & 0x7FFFFFFFu) : ~k;
    return __uint_as_float(u);
}

// ---------------------------------------------------------------------------
// K1: softmax over 81 classes per anchor; store 80 fg scores transposed.
// Thread enumeration is (lvl, a, pos) with pos fastest so that all class
// loads are warp-coalesced (consecutive lanes -> consecutive pos).
// ---------------------------------------------------------------------------
__global__ void __launch_bounds__(256)
k_softmax(const float* __restrict__ c0, const float* __restrict__ c1,
          const float* __restrict__ c2, const float* __restrict__ c3,
          const float* __restrict__ c4) {
    int t = blockIdx.x * 256 + threadIdx.x;
    int b = blockIdx.y;
    if (t >= NA) return;
    int lvl, u; get_lvl(t, lvl, u);          // same cumulative boundaries
    int HW = lvl_hw(lvl);
    int a = u / HW, pos = u - a * HW;        // lanes consecutive in pos
    const float* base = sel_ptr(lvl, c0, c1, c2, c3, c4)
                        + ((size_t)b * 243 + a * 81) * HW + pos;
    float m = -1e30f;
    #pragma unroll 4
    for (int c = 0; c < 81; c++) m = fmaxf(m, base[(size_t)c * HW]);
    float s = 0.f;
    #pragma unroll 4
    for (int c = 0; c < 81; c++) s += expf(base[(size_t)c * HW] - m);
    float inv = 1.0f / s;
    int A = (t - u) + pos * 3 + a;           // anchor index in canonical order
    float* o = g_scores + (size_t)b * NCLS * PITCH + A;
    #pragma unroll 4
    for (int c = 0; c < 80; c++)
        o[(size_t)c * PITCH] = expf(base[(size_t)c * HW] - m) * inv;
}

// ---------------------------------------------------------------------------
// K2: anchor generation (fp64, matching numpy) + delta2bbox decode.
// ---------------------------------------------------------------------------
__global__ void __launch_bounds__(256)
k_decode(const float* __restrict__ b0, const float* __restrict__ b1,
         const float* __restrict__ b2, const float* __restrict__ b3,
         const float* __restrict__ b4) {
    int A = blockIdx.x * 256 + threadIdx.x;
    int b = blockIdx.y;
    if (A >= NA) return;
    int lvl, i; get_lvl(A, lvl, i);
    int HW = lvl_hw(lvl), f = lvl_f(lvl), bs = lvl_bs(lvl);
    int pos = i / 3, a = i - pos * 3;
    int x = pos % f, y = pos / f;

    const double hrD[3] = {0.7071067811865476, 1.0, 1.4142135623730951};
    double hr = hrD[a], wr = 1.0 / hr;
    double bsd = (double)bs;
    double ws = bsd * wr * 3.0, hs = bsd * hr * 3.0;
    double c = bsd * 0.5;
    double sx = (double)(x * bs), sy = (double)(y * bs);
    float ax1 = (float)((c - 0.5 * ws) + sx);
    float ay1 = (float)((c - 0.5 * hs) + sy);
    float ax2 = (float)((c + 0.5 * ws) + sx);
    float ay2 = (float)((c + 0.5 * hs) + sy);

    const float* bp = sel_ptr(lvl, b0, b1, b2, b3, b4)
                      + ((size_t)b * 12 + a * 4) * HW + pos;
    float d0 = bp[0] * 0.1f;
    float d1 = bp[(size_t)HW] * 0.1f;
    float d2 = bp[(size_t)2 * HW] * 0.2f;
    float d3 = bp[(size_t)3 * HW] * 0.2f;

    float px = (ax1 + ax2) * 0.5f, py = (ay1 + ay2) * 0.5f;
    float pw = ax2 - ax1,          ph = ay2 - ay1;
    float dw = fminf(fmaxf(d2, -MAXR), MAXR);
    float dh = fminf(fmaxf(d3, -MAXR), MAXR);
    float gx = px + pw * d0;
    float gy = py + ph * d1;
    float gw = pw * expf(dw);
    float gh = ph * expf(dh);
    float x1 = fminf(fmaxf(gx - 0.5f * gw, 0.f), 320.f);
    float y1 = fminf(fmaxf(gy - 0.5f * gh, 0.f), 320.f);
    float x2 = fminf(fmaxf(gx + 0.5f * gw, 0.f), 320.f);
    float y2 = fminf(fmaxf(gy + 0.5f * gh, 0.f), 320.f);
    g_boxes[b * NA + A] = make_float4(x1, y1, x2, y2);
}

// ---------------------------------------------------------------------------
// K3: per-(batch,class) exact top-200 via 4-pass radix select + bitonic sort.
// Bin selection is a parallel suffix-sum (no serial 256-iteration scan).
// ---------------------------------------------------------------------------
__global__ void __launch_bounds__(256)
k_topk_class() {
    int c = blockIdx.x, b = blockIdx.y, tid = threadIdx.x;
    __shared__ unsigned sv[NA];
    __shared__ unsigned hist[256];
    __shared__ unsigned s_scan[256];
    __shared__ unsigned long long cand[256];
    __shared__ unsigned s_sel, s_k, s_cnt;

    const float* row = g_scores + (size_t)(b * NCLS + c) * PITCH;
    for (int i = tid; i < NA; i += 256) sv[i] = __float_as_uint(row[i]);  // scores>0

    unsigned prefix = 0, mask = 0;
    if (tid == 0) s_k = TOPK;
    __syncthreads();

    for (int shift = 24; shift >= 0; shift -= 8) {
        hist[tid] = 0; __syncthreads();
        for (int i = tid; i < NA; i += 256) {
            unsigned v = sv[i];
            if ((v & mask) == prefix) atomicAdd(&hist[(v >> shift) & 255], 1);
        }
        __syncthreads();
        unsigned h = hist[tid];
        s_scan[tid] = h; __syncthreads();
        // inclusive suffix sum: s_scan[t] = sum_{i>=t} hist[i]
        for (int d = 1; d < 256; d <<= 1) {
            unsigned v2 = (tid + d < 256) ? s_scan[tid + d] : 0;
            __syncthreads();
            s_scan[tid] += v2;
            __syncthreads();
        }
        unsigned k = s_k;
        unsigned suf = s_scan[tid];
        bool hit = (suf >= k) && (suf - h < k);     // exactly one thread
        __syncthreads();
        if (hit) { s_sel = (unsigned)tid; s_k = k - (suf - h); }
        __syncthreads();
        prefix |= s_sel << shift;
        mask   |= 0xFFu << shift;
        __syncthreads();
    }
    unsigned T = prefix, krem = s_k;     // take krem elements equal to T (lowest idx)
    if (tid == 0) s_cnt = 0;
    __syncthreads();

    for (int i = tid; i < NA; i += 256) {
        unsigned v = sv[i];
        if (v > T) {
            unsigned p = atomicAdd(&s_cnt, 1);
            cand[p] = ((unsigned long long)v << 32) | (unsigned)(~i);
        }
    }
    __syncthreads();
    unsigned cntgt = s_cnt;              // == TOPK - krem

    const int CH = (NA + 255) / 256;     // 26
    int lo = tid * CH, hi = min(lo + CH, NA);
    unsigned cnt = 0;
    for (int i = lo; i < hi; i++) if (sv[i] == T) cnt++;
    s_scan[tid] = cnt; __syncthreads();
    for (int d = 1; d < 256; d <<= 1) {
        unsigned t2 = (tid >= d) ? s_scan[tid - d] : 0;
        __syncthreads();
        s_scan[tid] += t2;
        __syncthreads();
    }
    unsigned r = (tid == 0) ? 0 : s_scan[tid - 1];
    for (int i = lo; i < hi; i++) {
        if (sv[i] == T) {
            if (r < krem) cand[cntgt + r] = ((unsigned long long)T << 32) | (unsigned)(~i);
            r++;
        }
    }
    if (tid >= TOPK) cand[tid] = 0ULL;   // pad 200..255
    __syncthreads();

    // bitonic sort 256, descending (keys unique -> stability irrelevant)
    for (int size = 2; size <= 256; size <<= 1)
        for (int stride = size >> 1; stride > 0; stride >>= 1) {
            __syncthreads();
            int j = tid ^ stride;
            if (j > tid) {
                bool desc = ((tid & size) == 0);
                unsigned long long a = cand[tid], bb = cand[j];
                if ((a < bb) == desc) { cand[tid] = bb; cand[j] = a; }
            }
        }
    __syncthreads();

    if (tid < TOPK) {
        unsigned long long kk = cand[tid];
        int base = (b * NCLS + c) * TOPK + tid;
        g_order[base]  = (int)(~(unsigned)kk);
        g_tscore[base] = __uint_as_float((unsigned)(kk >> 32));
    }
}

// ---------------------------------------------------------------------------
// K4: fast-NMS, division-free but bit-identical to RN(ov/un) <= 0.5:
//   RN(ov/un) <= 0.5  <=>  ov/un <= 0.5 + 2^-25  <=>  fma(-0.5,un,ov) <= 2^-25*un
// (near the boundary ov in [0.25*un, un] so the fma is Sterbenz-exact, and
//  2^-25*un is an exact scale). Areas are precomputed in shared.
// ---------------------------------------------------------------------------
__global__ void __launch_bounds__(256)
k_nms() {
    int c = blockIdx.x, b = blockIdx.y, tid = threadIdx.x;
    __shared__ float4 sb[TOPK];
    __shared__ float  sa[TOPK];
    int base = (b * NCLS + c) * TOPK;
    if (tid < TOPK) {
        int a = g_order[base + tid];
        float4 bx = g_boxes[b * NA + a];
        sb[tid] = bx;
        sa[tid] = (bx.z - bx.x) * (bx.w - bx.y);
    }
    __syncthreads();
    if (tid < TOPK) {
        float4 bj = sb[tid];
        float aj = sa[tid];
        float m = -1.0f;                       // max_i (lhs_i - rhs_i)
        #pragma unroll 4
        for (int i = 0; i < tid; i++) {
            float4 bi = sb[i];
            float lx = fmaxf(bi.x, bj.x), ly = fmaxf(bi.y, bj.y);
            float rx = fminf(bi.z, bj.z), ry = fminf(bi.w, bj.w);
            float w  = fmaxf(rx - lx, 0.f), h = fmaxf(ry - ly, 0.f);
            float ov = w * h;
            float un = fmaxf((sa[i] + aj) - ov, 1e-6f);
            float lhs = fmaf(-IOU_THR, un, ov);     // ov - 0.5*un (exact near bound)
            float rhs = un * HALF_ULP;              // exact
            m = fmaxf(m, lhs - rhs);                // exact sign near bound
        }
        float s = g_tscore[base + tid];
        bool keep = (m <= 0.0f) && (s > SCORE_THR);
        g_tscore[base + tid] = keep ? s : -1.0f;
    }
}

// ---------------------------------------------------------------------------
// K5: per-batch global top-100 over 16000 masked scores (lax.top_k semantics).
// ---------------------------------------------------------------------------
__global__ void __launch_bounds__(256)
k_topk_final() {
    int b = blockIdx.x, tid = threadIdx.x;
    const float* vals = g_tscore + (size_t)b * NFLAT;
    __shared__ unsigned hist[256];
    __shared__ unsigned s_scan[256];
    __shared__ unsigned long long cand[128];
    __shared__ unsigned s_sel, s_k, s_cnt;

    unsigned prefix = 0, mask = 0;
    if (tid == 0) s_k = MAXNUM;
    __syncthreads();

    for (int shift = 24; shift >= 0; shift -= 8) {
        hist[tid] = 0; __syncthreads();
        for (int i = tid; i < NFLAT; i += 256) {
            unsigned v = f2key(vals[i]);
            if ((v & mask) == prefix) atomicAdd(&hist[(v >> shift) & 255], 1);
        }
        __syncthreads();
        unsigned h = hist[tid];
        s_scan[tid] = h; __syncthreads();
        for (int d = 1; d < 256; d <<= 1) {
            unsigned v2 = (tid + d < 256) ? s_scan[tid + d] : 0;
            __syncthreads();
            s_scan[tid] += v2;
            __syncthreads();
        }
        unsigned k = s_k;
        unsigned suf = s_scan[tid];
        bool hit = (suf >= k) && (suf - h < k);
        __syncthreads();
        if (hit) { s_sel = (unsigned)tid; s_k = k - (suf - h); }
        __syncthreads();
        prefix |= s_sel << shift;
        mask   |= 0xFFu << shift;
        __syncthreads();
    }
    unsigned T = prefix, krem = s_k;
    if (tid == 0) s_cnt = 0;
    __syncthreads();

    for (int i = tid; i < NFLAT; i += 256) {
        unsigned v = f2key(vals[i]);
        if (v > T) {
            unsigned p = atomicAdd(&s_cnt, 1);
            cand[p] = ((unsigned long long)v << 32) | (unsigned)(~i);
        }
    }
    __syncthreads();
    unsigned cntgt = s_cnt;

    const int CH = (NFLAT + 255) / 256;  // 63
    int lo = tid * CH, hi = min(lo + CH, NFLAT);
    unsigned cnt = 0;
    for (int i = lo; i < hi; i++) if (f2key(vals[i]) == T) cnt++;
    s_scan[tid] = cnt; __syncthreads();
    for (int d = 1; d < 256; d <<= 1) {
        unsigned t2 = (tid >= d) ? s_scan[tid - d] : 0;
        __syncthreads();
        s_scan[tid] += t2;
        __syncthreads();
    }
    unsigned r = (tid == 0) ? 0 : s_scan[tid - 1];
    for (int i = lo; i < hi; i++) {
        if (f2key(vals[i]) == T) {
            if (r < krem) cand[cntgt + r] = ((unsigned long long)T << 32) | (unsigned)(~i);
            r++;
        }
    }
    if (tid >= MAXNUM && tid < 128) cand[tid] = 0ULL;
    __syncthreads();

    for (int size = 2; size <= 128; size <<= 1)
        for (int stride = size >> 1; stride > 0; stride >>= 1) {
            __syncthreads();
            if (tid < 128) {
                int j = tid ^ stride;
                if (j > tid) {
                    bool desc = ((tid & size) == 0);
                    unsigned long long a = cand[tid], bb = cand[j];
                    if ((a < bb) == desc) { cand[tid] = bb; cand[j] = a; }
                }
            }
        }
    __syncthreads();

    if (tid < MAXNUM) {
        unsigned long long kk = cand[tid];
        g_selidx[b * MAXNUM + tid] = (int)(~(unsigned)kk);
        g_selval[b * MAXNUM + tid] = key2f((unsigned)(kk >> 32));
    }
}

// ---------------------------------------------------------------------------
// K6: gather cls_dets, labels, and the 32 mask coefficients per detection.
// ---------------------------------------------------------------------------
__global__ void __launch_bounds__(128)
k_gather(const float* __restrict__ f0, const float* __restrict__ f1,
         const float* __restrict__ f2, const float* __restrict__ f3,
         const float* __restrict__ f4, float* __restrict__ out) {
    int b = blockIdx.x, tid = threadIdx.x;
    if (tid >= MAXNUM) return;
    int flat = g_selidx[b * MAXNUM + tid];
    int cls = flat / TOPK, k = flat - cls * TOPK;
    int a = g_order[(b * NCLS + cls) * TOPK + k];
    float4 box = g_boxes[b * NA + a];
    float v = g_selval[b * MAXNUM + tid];

    float* det = out + (size_t)b * MAXNUM * 5 + (size_t)tid * 5;
    det[0] = box.x; det[1] = box.y; det[2] = box.z; det[3] = box.w; det[4] = v;
    out[OFF_LAB + (size_t)b * MAXNUM + tid] = (float)cls;

    int lvl, i; get_lvl(a, lvl, i);
    int HW = lvl_hw(lvl);
    int pos = i / 3, ar = i - pos * 3;
    const float* cp = sel_ptr(lvl, f0, f1, f2, f3, f4)
                      + ((size_t)b * 96 + ar * 32) * HW + pos;
    float* gc = g_coeff + ((size_t)b * MAXNUM + tid) * NCOEF;
    #pragma unroll
    for (int c = 0; c < NCOEF; c++) gc[c] = cp[(size_t)c * HW];
}

// ---------------------------------------------------------------------------
// K7: masks = sigmoid(proto[80,80,32] @ coeff[100,32]^T) -> [80,80,100].
// Thread = one pixel (proto row in registers), coeffs broadcast from smem as
// float4, output staged through smem in 25-det chunks.
// ---------------------------------------------------------------------------
__global__ void __launch_bounds__(256)
k_masks(const float* __restrict__ proto, float* __restrict__ out) {
    __shared__ float scoef[MAXNUM * NCOEF];   // 12.8 KB
    __shared__ float sout[256 * 25];          // 25.6 KB
    int b = blockIdx.y;
    int pixbase = blockIdx.x * 256;
    int tid = threadIdx.x;

    for (int i = tid; i < MAXNUM * NCOEF; i += 256)
        scoef[i] = g_coeff[(size_t)b * MAXNUM * NCOEF + i];
    __syncthreads();

    float pr[NCOEF];
    const float* pp = proto + ((size_t)b * NPIX + pixbase + tid) * NCOEF;
    #pragma unroll
    for (int c = 0; c < NCOEF; c += 4) {
        float4 t = *reinterpret_cast<const float4*>(pp + c);
        pr[c] = t.x; pr[c + 1] = t.y; pr[c + 2] = t.z; pr[c + 3] = t.w;
    }

    float* outm = out + OFF_MASK + (size_t)b * NPIX * MAXNUM;
    for (int chunk = 0; chunk < 4; chunk++) {
        int dbase = chunk * 25;
        for (int d = 0; d < 25; d++) {
            const float4* cf4 = reinterpret_cast<const float4*>(scoef + (dbase + d) * NCOEF);
            float acc = 0.f;
            #pragma unroll
            for (int q = 0; q < 8; q++) {
                float4 t4 = cf4[q];                       // LDS.128 broadcast
                acc = fmaf(pr[4*q + 0], t4.x, acc);
                acc = fmaf(pr[4*q + 1], t4.y, acc);
                acc = fmaf(pr[4*q + 2], t4.z, acc);
                acc = fmaf(pr[4*q + 3], t4.w, acc);
            }
            sout[tid * 25 + d] = 1.0f / (1.0f + expf(-acc));
        }
        __syncthreads();
        for (int i = tid; i < 256 * 25; i += 256) {
            int p = i / 25, d = i - p * 25;
            outm[(size_t)(pixbase + p) * MAXNUM + dbase + d] = sout[i];
        }
        __syncthreads();
    }
}

// ---------------------------------------------------------------------------
extern "C" void kernel_launch(void* const* d_in, const int* in_sizes, int n_in,
                              void* d_out, int out_size) {
    const float* cs[5]; const float* bp[5]; const float* cf[5];
    for (int i = 0; i < 5; i++) {
        cs[i] = (const float*)d_in[i];
        bp[i] = (const float*)d_in[5 + i];
        cf[i] = (const float*)d_in[10 + i];
    }
    const float* proto = (const float*)d_in[15];
    float* out = (float*)d_out;

    dim3 gA((NA + 255) / 256, NBATCH);
    k_softmax   <<<gA, 256>>>(cs[0], cs[1], cs[2], cs[3], cs[4]);
    k_decode    <<<gA, 256>>>(bp[0], bp[1], bp[2], bp[3], bp[4]);
    k_topk_class<<<dim3(NCLS, NBATCH), 256>>>();
    k_nms       <<<dim3(NCLS, NBATCH), 256>>>();
    k_topk_final<<<NBATCH, 256>>>();
    k_gather    <<<NBATCH, 128>>>(cf[0], cf[1], cf[2], cf[3], cf[4], out);
    k_masks     <<<dim3(NPIX / 256, NBATCH), 256>>>(proto, out);
}